// round 3
// baseline (speedup 1.0000x reference)
#include <cuda_runtime.h>
#include <cuda_bf16.h>

// PrecisionFocusedLoss: mean over B of ce(logits, t) * (1 + 3*penalty(t, argmax))
// C = 2:
//   u  = x1 - x0
//   ce = softplus(t ? -u : u)
//   w  : t=0: u>0 -> 16 (FP), else 1.3 ; t=1: u>0 -> 1.3, else 4 (FN)
// tie (u==0) -> pred = 0 (strict u > 0).
//
// Single kernel, last-block-finalizes. 8 samples per thread-iteration:
// 6 independent 16B streaming loads front-batched for high MLP.

#define NBLOCKS (148 * 8)   // exactly 8 blocks per SM, single balanced wave
#define NTHREADS 256

__device__ double g_partials[NBLOCKS];
__device__ unsigned int g_done_count;   // zero-init; reset by finalizer each run

#define W_LOW  1.3000000119209290f      // 1 + 3*0.1 in f32 rounding
#define W_FN   4.0f
#define W_FP   16.0f

__device__ __forceinline__ float sample_loss(float x0, float x1, int t) {
    float u = x1 - x0;
    float z = t ? -u : u;
    float e = __expf(-fabsf(z));
    float ce = fmaxf(z, 0.0f) + __logf(1.0f + e);
    float w;
    if (t) w = (u > 0.0f) ? W_LOW : W_FN;
    else   w = (u > 0.0f) ? W_FP  : W_LOW;
    return ce * w;
}

__global__ void __launch_bounds__(NTHREADS)
loss_fused(const float4* __restrict__ l4, const int4* __restrict__ t4,
           int nr, const float* __restrict__ logits,
           const int* __restrict__ targets, int n, float* __restrict__ out) {
    float acc = 0.0f;
    const int stride = gridDim.x * blockDim.x;

    // Each r = 8 samples: logits l4[4r..4r+3], targets t4[2r..2r+1].
    for (int r = blockIdx.x * blockDim.x + threadIdx.x; r < nr; r += stride) {
        // Front-batch 6 independent streaming loads (96 B in flight).
        float4 L0 = __ldcs(&l4[4 * r + 0]);
        float4 L1 = __ldcs(&l4[4 * r + 1]);
        float4 L2 = __ldcs(&l4[4 * r + 2]);
        float4 L3 = __ldcs(&l4[4 * r + 3]);
        int4   T0 = __ldcs(&t4[2 * r + 0]);
        int4   T1 = __ldcs(&t4[2 * r + 1]);

        acc += sample_loss(L0.x, L0.y, T0.x);
        acc += sample_loss(L0.z, L0.w, T0.y);
        acc += sample_loss(L1.x, L1.y, T0.z);
        acc += sample_loss(L1.z, L1.w, T0.w);
        acc += sample_loss(L2.x, L2.y, T1.x);
        acc += sample_loss(L2.z, L2.w, T1.y);
        acc += sample_loss(L3.x, L3.y, T1.z);
        acc += sample_loss(L3.z, L3.w, T1.w);
    }
    // Tail (n % 8 != 0) — one thread, before the reduce.
    if (blockIdx.x == 0 && threadIdx.x == 0) {
        for (int i = nr * 8; i < n; i++)
            acc += sample_loss(logits[2 * i], logits[2 * i + 1], targets[i]);
    }

    // ── Block reduction ──
    __shared__ float warp_sums[NTHREADS / 32];
    #pragma unroll
    for (int o = 16; o > 0; o >>= 1)
        acc += __shfl_down_sync(0xffffffffu, acc, o);
    if ((threadIdx.x & 31) == 0)
        warp_sums[threadIdx.x >> 5] = acc;
    __syncthreads();

    __shared__ bool is_last;
    if (threadIdx.x == 0) {
        float v = 0.0f;
        #pragma unroll
        for (int i = 0; i < NTHREADS / 32; i++) v += warp_sums[i];
        g_partials[blockIdx.x] = (double)v;
        __threadfence();
        unsigned int c = atomicAdd(&g_done_count, 1u);
        is_last = (c == gridDim.x - 1);
    }
    __syncthreads();

    // ── Last block finalizes (deterministic fixed-order sum) ──
    if (is_last) {
        __shared__ double dsum[NTHREADS / 32];
        double v = 0.0;
        for (int i = threadIdx.x; i < NBLOCKS; i += NTHREADS)
            v += g_partials[i];
        #pragma unroll
        for (int o = 16; o > 0; o >>= 1)
            v += __shfl_down_sync(0xffffffffu, v, o);
        if ((threadIdx.x & 31) == 0)
            dsum[threadIdx.x >> 5] = v;
        __syncthreads();
        if (threadIdx.x < 32) {
            double s = (threadIdx.x < NTHREADS / 32) ? dsum[threadIdx.x] : 0.0;
            #pragma unroll
            for (int o = (NTHREADS / 32) / 2; o > 0; o >>= 1)
                s += __shfl_down_sync(0xffffffffu, s, o);
            if (threadIdx.x == 0) {
                out[0] = (float)(s / (double)n);
                g_done_count = 0;
            }
        }
    }
}

extern "C" void kernel_launch(void* const* d_in, const int* in_sizes, int n_in,
                              void* d_out, int out_size) {
    const float* logits  = (const float*)d_in[0];   // (B, 2) f32
    const int*   targets = (const int*)d_in[1];     // (B,)   i32
    const int    n  = in_sizes[1];
    const int    nr = n >> 3;                       // groups of 8 samples

    loss_fused<<<NBLOCKS, NTHREADS>>>(
        (const float4*)logits, (const int4*)targets, nr, logits, targets, n,
        (float*)d_out);
}

// round 4
// speedup vs baseline: 1.5484x; 1.5484x over previous
#include <cuda_runtime.h>
#include <cuda_bf16.h>

// PrecisionFocusedLoss: mean over B of ce(logits, t) * (1 + 3*penalty(t, argmax))
// C = 2:
//   u  = x1 - x0
//   ce = softplus(t ? -u : u)
//   w  : t=0: u>0 -> 16 (FP), else 1.3 ; t=1: u>0 -> 1.3, else 4 (FN)
// tie (u==0) -> pred = 0 (strict u > 0).
//
// Single kernel, last-block-finalizes. 4 samples/iter (3 front-batched 16B
// loads, MLP_p1=3) at 4 CTAs/SM: keeps oe*MLP_p1 = 12 below the B300
// L1tex-queue contention threshold (~16) that killed R3.

#define NBLOCKS (148 * 4)   // 592: exactly 4 blocks/SM, single balanced wave
#define NTHREADS 256

__device__ double g_partials[NBLOCKS];
__device__ unsigned int g_done_count;   // zero-init; reset by finalizer each run

#define W_LOW  1.3000000119209290f      // 1 + 3*0.1 in f32 rounding
#define W_FN   4.0f
#define W_FP   16.0f

__device__ __forceinline__ float sample_loss(float x0, float x1, int t) {
    float u = x1 - x0;
    float z = t ? -u : u;
    float e = __expf(-fabsf(z));
    float ce = fmaxf(z, 0.0f) + __logf(1.0f + e);
    float w;
    if (t) w = (u > 0.0f) ? W_LOW : W_FN;
    else   w = (u > 0.0f) ? W_FP  : W_LOW;
    return ce * w;
}

__global__ void __launch_bounds__(NTHREADS)
loss_fused(const float4* __restrict__ l4, const int4* __restrict__ t4,
           int nq, const float* __restrict__ logits,
           const int* __restrict__ targets, int n, float* __restrict__ out) {
    float acc = 0.0f;
    const int stride = gridDim.x * blockDim.x;
    for (int q = blockIdx.x * blockDim.x + threadIdx.x; q < nq; q += stride) {
        // 4 samples: 2 x float4 logits + 1 x int4 targets (3 independent loads)
        float4 L0 = l4[2 * q];
        float4 L1 = l4[2 * q + 1];
        int4   T  = t4[q];
        acc += sample_loss(L0.x, L0.y, T.x);
        acc += sample_loss(L0.z, L0.w, T.y);
        acc += sample_loss(L1.x, L1.y, T.z);
        acc += sample_loss(L1.z, L1.w, T.w);
    }
    // Tail (n % 4 != 0) — one thread, before the reduce.
    if (blockIdx.x == 0 && threadIdx.x == 0) {
        for (int i = nq * 4; i < n; i++)
            acc += sample_loss(logits[2 * i], logits[2 * i + 1], targets[i]);
    }

    // ── Block reduction ──
    __shared__ float warp_sums[NTHREADS / 32];
    #pragma unroll
    for (int o = 16; o > 0; o >>= 1)
        acc += __shfl_down_sync(0xffffffffu, acc, o);
    if ((threadIdx.x & 31) == 0)
        warp_sums[threadIdx.x >> 5] = acc;
    __syncthreads();

    __shared__ bool is_last;
    if (threadIdx.x == 0) {
        float v = 0.0f;
        #pragma unroll
        for (int i = 0; i < NTHREADS / 32; i++) v += warp_sums[i];
        g_partials[blockIdx.x] = (double)v;
        __threadfence();
        unsigned int c = atomicAdd(&g_done_count, 1u);
        is_last = (c == gridDim.x - 1);
    }
    __syncthreads();

    // ── Last block finalizes (deterministic fixed-order sum) ──
    if (is_last) {
        __shared__ double dsum[NTHREADS / 32];
        double v = 0.0;
        for (int i = threadIdx.x; i < NBLOCKS; i += NTHREADS)
            v += g_partials[i];
        #pragma unroll
        for (int o = 16; o > 0; o >>= 1)
            v += __shfl_down_sync(0xffffffffu, v, o);
        if ((threadIdx.x & 31) == 0)
            dsum[threadIdx.x >> 5] = v;
        __syncthreads();
        if (threadIdx.x < 32) {
            double s = (threadIdx.x < NTHREADS / 32) ? dsum[threadIdx.x] : 0.0;
            #pragma unroll
            for (int o = (NTHREADS / 32) / 2; o > 0; o >>= 1)
                s += __shfl_down_sync(0xffffffffu, s, o);
            if (threadIdx.x == 0) {
                out[0] = (float)(s / (double)n);
                g_done_count = 0;
            }
        }
    }
}

extern "C" void kernel_launch(void* const* d_in, const int* in_sizes, int n_in,
                              void* d_out, int out_size) {
    const float* logits  = (const float*)d_in[0];   // (B, 2) f32
    const int*   targets = (const int*)d_in[1];     // (B,)   i32
    const int    n  = in_sizes[1];
    const int    nq = n >> 2;

    loss_fused<<<NBLOCKS, NTHREADS>>>(
        (const float4*)logits, (const int4*)targets, nq, logits, targets, n,
        (float*)d_out);
}

// round 5
// speedup vs baseline: 1.5517x; 1.0022x over previous
#include <cuda_runtime.h>
#include <cuda_bf16.h>

// PrecisionFocusedLoss: mean over B of ce(logits, t) * (1 + 3*penalty(t, argmax))
// C = 2:
//   u  = x1 - x0
//   ce = softplus(t ? -u : u)
//   w  : t=0: u>0 -> 16 (FP), else 1.3 ; t=1: u>0 -> 1.3, else 4 (FN)
// tie (u==0) -> pred = 0 (strict u > 0).
//
// Single kernel, last-block-finalizes. Dual-stream software pipeline:
// each thread handles one quad from each half of the domain per iteration
// -> 6 independent LDG.128 front-batched (MLP 6) while keeping the 32B
// lane stride (8 x 128B lines per LDG) that R2/R4 validated.

#define NBLOCKS (148 * 4)   // 592: exactly 4 blocks/SM, single balanced wave
#define NTHREADS 256

__device__ double g_partials[NBLOCKS];
__device__ unsigned int g_done_count;   // zero-init; reset by finalizer each run

#define W_LOW  1.3000000119209290f      // 1 + 3*0.1 in f32 rounding
#define W_FN   4.0f
#define W_FP   16.0f

__device__ __forceinline__ float sample_loss(float x0, float x1, int t) {
    float u = x1 - x0;
    float z = t ? -u : u;
    float e = __expf(-fabsf(z));
    float ce = fmaxf(z, 0.0f) + __logf(1.0f + e);
    float w;
    if (t) w = (u > 0.0f) ? W_LOW : W_FN;
    else   w = (u > 0.0f) ? W_FP  : W_LOW;
    return ce * w;
}

__device__ __forceinline__ float quad_loss(float4 L0, float4 L1, int4 T) {
    float s = sample_loss(L0.x, L0.y, T.x);
    s += sample_loss(L0.z, L0.w, T.y);
    s += sample_loss(L1.x, L1.y, T.z);
    s += sample_loss(L1.z, L1.w, T.w);
    return s;
}

__global__ void __launch_bounds__(NTHREADS)
loss_fused(const float4* __restrict__ l4, const int4* __restrict__ t4,
           int nq, const float* __restrict__ logits,
           const int* __restrict__ targets, int n, float* __restrict__ out) {
    float acc = 0.0f;
    const int stride = gridDim.x * blockDim.x;
    const int half = nq >> 1;            // quads per half-domain

    // Dual stream: quad q (first half) + quad half+q (second half) per iter.
    for (int q = blockIdx.x * blockDim.x + threadIdx.x; q < half; q += stride) {
        const int qb = half + q;
        // 6 independent 16B loads, front-batched.
        float4 A0 = l4[2 * q];
        float4 A1 = l4[2 * q + 1];
        int4   TA = t4[q];
        float4 B0 = l4[2 * qb];
        float4 B1 = l4[2 * qb + 1];
        int4   TB = t4[qb];
        acc += quad_loss(A0, A1, TA);
        acc += quad_loss(B0, B1, TB);
    }
    // Middle leftover quad (nq odd) + scalar tail (n % 4) — one thread.
    if (blockIdx.x == 0 && threadIdx.x == 0) {
        if (nq & 1) {
            int q = 2 * half;            // == nq - 1
            acc += quad_loss(l4[2 * q], l4[2 * q + 1], t4[q]);
        }
        for (int i = nq * 4; i < n; i++)
            acc += sample_loss(logits[2 * i], logits[2 * i + 1], targets[i]);
    }

    // ── Block reduction ──
    __shared__ float warp_sums[NTHREADS / 32];
    #pragma unroll
    for (int o = 16; o > 0; o >>= 1)
        acc += __shfl_down_sync(0xffffffffu, acc, o);
    if ((threadIdx.x & 31) == 0)
        warp_sums[threadIdx.x >> 5] = acc;
    __syncthreads();

    __shared__ bool is_last;
    if (threadIdx.x == 0) {
        float v = 0.0f;
        #pragma unroll
        for (int i = 0; i < NTHREADS / 32; i++) v += warp_sums[i];
        g_partials[blockIdx.x] = (double)v;
        __threadfence();
        unsigned int c = atomicAdd(&g_done_count, 1u);
        is_last = (c == gridDim.x - 1);
    }
    __syncthreads();

    // ── Last block finalizes (deterministic fixed-order sum) ──
    if (is_last) {
        __shared__ double dsum[NTHREADS / 32];
        double v = 0.0;
        for (int i = threadIdx.x; i < NBLOCKS; i += NTHREADS)
            v += g_partials[i];
        #pragma unroll
        for (int o = 16; o > 0; o >>= 1)
            v += __shfl_down_sync(0xffffffffu, v, o);
        if ((threadIdx.x & 31) == 0)
            dsum[threadIdx.x >> 5] = v;
        __syncthreads();
        if (threadIdx.x < 32) {
            double s = (threadIdx.x < NTHREADS / 32) ? dsum[threadIdx.x] : 0.0;
            #pragma unroll
            for (int o = (NTHREADS / 32) / 2; o > 0; o >>= 1)
                s += __shfl_down_sync(0xffffffffu, s, o);
            if (threadIdx.x == 0) {
                out[0] = (float)(s / (double)n);
                g_done_count = 0;
            }
        }
    }
}

extern "C" void kernel_launch(void* const* d_in, const int* in_sizes, int n_in,
                              void* d_out, int out_size) {
    const float* logits  = (const float*)d_in[0];   // (B, 2) f32
    const int*   targets = (const int*)d_in[1];     // (B,)   i32
    const int    n  = in_sizes[1];
    const int    nq = n >> 2;

    loss_fused<<<NBLOCKS, NTHREADS>>>(
        (const float4*)logits, (const int4*)targets, nq, logits, targets, n,
        (float*)d_out);
}